// round 7
// baseline (speedup 1.0000x reference)
#include <cuda_runtime.h>
#include <math.h>

// Spherization, per row r (512 features):
//   ang_j = A*sigmoid(scaling*x) + phiL
//   out[k]   = radius * prod_{j<k}(sin(ang_j)+eps) * sgn(cos_k)*(|cos(ang_k)|+eps)
//   out[512] = radius * prod_j (sin(ang_j)+eps)
// R6 pipeline (MUFU.TANH sigmoid: sigmoid(z)=(1+tanh(z/2))/2), with occupancy
// retune: 4 warps/CTA -> 16 CTAs/SM (fills regfile + warp slots exactly),
// unguarded readback, streaming input loads.
// One warp per row; lane owns k = 128j+4l+m; 4 chained warp scans;
// SMEM-staged coalesced stores.

#define NFEAT 512
#define ROW_OUT 513
#define SROW_PITCH 520   // floats; 16B-aligned pitch
#define WARPS_PER_BLOCK 4
#define EPSf 1e-6f

__global__ __launch_bounds__(WARPS_PER_BLOCK * 32)
void spherization_kernel(const float* __restrict__ x,
                         const float* __restrict__ scaling_p,
                         const float* __restrict__ radius_p,
                         float* __restrict__ out,
                         int nrows, float halfA, float mid)
{
    __shared__ float sbuf[WARPS_PER_BLOCK * SROW_PITCH];

    const int wib  = threadIdx.x >> 5;
    const int lane = threadIdx.x & 31;
    const int row  = blockIdx.x * WARPS_PER_BLOCK + wib;
    if (row >= nrows) return;

    const float scaling = __ldg(scaling_p);
    const float radius  = __ldg(radius_p);
    const float hmul = 0.5f * scaling;     // t = hmul*x ; u = tanh(t)

    const float4* xr = reinterpret_cast<const float4*>(x + (size_t)row * NFEAT);
    float* srow = sbuf + wib * SROW_PITCH;

    // prefetch all loads (MLP=4), streaming (read-once)
    float4 v[4];
    #pragma unroll
    for (int j = 0; j < 4; j++) v[j] = __ldcs(&xr[lane + 32 * j]);

    float carry = radius;   // radius * (product of all elements in completed blocks)

    #pragma unroll
    for (int j = 0; j < 4; j++) {
        float vv[4] = {v[j].x, v[j].y, v[j].z, v[j].w};
        float sv[4], cv[4];
        #pragma unroll
        for (int m = 0; m < 4; m++) {
            float t = vv[m] * hmul;
            float u;  asm("tanh.approx.f32 %0, %1;" : "=f"(u) : "f"(t));
            float ang = fmaf(halfA, u, mid);          // in [phiL, pi - phiL]
            float sn  = __sinf(ang);                  // > 0 on range
            float cs  = __cosf(ang);
            sv[m] = sn + EPSf;
            cv[m] = copysignf(fabsf(cs) + EPSf, cs);
        }
        // local exclusive prefixes within the 4 owned elements
        float e1  = sv[0];
        float e2  = e1 * sv[1];
        float e3  = e2 * sv[2];
        float tot = e3 * sv[3];

        // warp-inclusive scan of per-lane block totals
        float incl = tot;
        #pragma unroll
        for (int d = 1; d < 32; d <<= 1) {
            float t2 = __shfl_up_sync(0xFFFFFFFFu, incl, d);
            if (lane >= d) incl *= t2;
        }
        float excl = __shfl_up_sync(0xFFFFFFFFu, incl, 1);
        if (lane == 0) excl = 1.0f;

        float bp = carry * excl;  // radius * prod of everything before this lane

        float4 o;
        o.x = bp * cv[0];
        o.y = (bp * e1) * cv[1];
        o.z = (bp * e2) * cv[2];
        o.w = (bp * e3) * cv[3];
        reinterpret_cast<float4*>(srow)[lane + 32 * j] = o;

        carry *= __shfl_sync(0xFFFFFFFFu, incl, 31);
    }
    if (lane == 0) srow[NFEAT] = carry;   // out[512] = radius * full product
    __syncwarp();

    // coalesced copy SMEM row -> GMEM (row pitch 513 floats)
    float* orow = out + (size_t)row * ROW_OUT;
    #pragma unroll
    for (int it = 0; it < 16; it++)
        orow[lane + 32 * it] = srow[lane + 32 * it];
    if (lane == 0) orow[NFEAT] = srow[NFEAT];
}

extern "C" void kernel_launch(void* const* d_in, const int* in_sizes, int n_in,
                              void* d_out, int out_size)
{
    int xi = 0;
    for (int i = 0; i < n_in; i++) if (in_sizes[i] > in_sizes[xi]) xi = i;
    int others[2]; int no = 0;
    for (int i = 0; i < n_in && no < 2; i++) if (i != xi) others[no++] = i;

    const float* x   = (const float*)d_in[xi];
    const float* sc  = (const float*)d_in[others[0]];   // scaling
    const float* rad = (const float*)d_in[others[1]];   // radius

    float* out = (float*)d_out;
    int nrows = in_sizes[xi] / NFEAT;

    // constants in double; PI truncated exactly as in the reference
    const double PI_d = 3.141592;
    double phiL = asin(pow(1e-6, 1.0 / 512.0));
    double phiU = PI_d / 2.0 * (1.0 - 0.01);
    if (phiU < phiL) phiL = phiU;
    double A = PI_d - 2.0 * phiL;
    float halfA = (float)(0.5 * A);          // ang = halfA*u + (halfA + phiL)
    float mid   = (float)(0.5 * A + phiL);

    int blocks = (nrows + WARPS_PER_BLOCK - 1) / WARPS_PER_BLOCK;
    spherization_kernel<<<blocks, WARPS_PER_BLOCK * 32>>>(
        x, sc, rad, out, nrows, halfA, mid);
}

// round 8
// speedup vs baseline: 1.0418x; 1.0418x over previous
#include <cuda_runtime.h>
#include <math.h>

// Spherization, per row r (512 features):
//   ang_j = A*sigmoid(scaling*x) + phiL
//   out[k]   = radius * prod_{j<k}(sin(ang_j)+eps) * sgn(cos_k)*(|cos(ang_k)|+eps)
//   out[512] = radius * prod_j (sin(ang_j)+eps)
// R6 pipeline (MUFU.TANH sigmoid: sigmoid(z)=(1+tanh(z/2))/2, then MUFU.SIN/COS),
// WPB=8 / plain LDG.128 prefetch (best measured), plus:
//  - 4 INDEPENDENT warp scans (ILP-4 on the shfl critical path)
//  - unguarded readback (16 iters + lane0 tail)

#define NFEAT 512
#define ROW_OUT 513
#define SROW_PITCH 520   // floats; 16B-aligned pitch
#define WARPS_PER_BLOCK 8
#define EPSf 1e-6f

__global__ __launch_bounds__(WARPS_PER_BLOCK * 32)
void spherization_kernel(const float* __restrict__ x,
                         const float* __restrict__ scaling_p,
                         const float* __restrict__ radius_p,
                         float* __restrict__ out,
                         int nrows, float halfA, float mid)
{
    __shared__ float sbuf[WARPS_PER_BLOCK * SROW_PITCH];

    const int wib  = threadIdx.x >> 5;
    const int lane = threadIdx.x & 31;
    const int row  = blockIdx.x * WARPS_PER_BLOCK + wib;
    if (row >= nrows) return;

    const float scaling = __ldg(scaling_p);
    const float radius  = __ldg(radius_p);
    const float hmul = 0.5f * scaling;     // t = hmul*x ; u = tanh(t)

    const float4* xr = reinterpret_cast<const float4*>(x + (size_t)row * NFEAT);
    float* srow = sbuf + wib * SROW_PITCH;

    // prefetch all loads (MLP=4)
    float4 v[4];
    #pragma unroll
    for (int j = 0; j < 4; j++) v[j] = xr[lane + 32 * j];

    float e1a[4], e2a[4], e3a[4];           // local prefix pieces per block
    float cv0[4], cv1[4], cv2[4], cv3[4];   // cos terms per block
    float tot[4];                           // per-lane block totals

    #pragma unroll
    for (int j = 0; j < 4; j++) {
        float vv[4] = {v[j].x, v[j].y, v[j].z, v[j].w};
        float sv[4], cv[4];
        #pragma unroll
        for (int m = 0; m < 4; m++) {
            float t = vv[m] * hmul;
            float u;  asm("tanh.approx.f32 %0, %1;" : "=f"(u) : "f"(t));
            float ang = fmaf(halfA, u, mid);          // in [phiL, pi - phiL]
            float sn  = __sinf(ang);                  // > 0 on range
            float cs  = __cosf(ang);
            sv[m] = sn + EPSf;
            cv[m] = copysignf(fabsf(cs) + EPSf, cs);
        }
        float e1 = sv[0];
        float e2 = e1 * sv[1];
        float e3 = e2 * sv[2];
        e1a[j] = e1; e2a[j] = e2; e3a[j] = e3;
        tot[j] = e3 * sv[3];
        cv0[j] = cv[0]; cv1[j] = cv[1]; cv2[j] = cv[2]; cv3[j] = cv[3];
    }

    // 4 INDEPENDENT warp-inclusive scans of block totals (ILP-4 shfl chains)
    float i0 = tot[0], i1 = tot[1], i2 = tot[2], i3 = tot[3];
    #pragma unroll
    for (int d = 1; d < 32; d <<= 1) {
        float t0 = __shfl_up_sync(0xFFFFFFFFu, i0, d);
        float t1 = __shfl_up_sync(0xFFFFFFFFu, i1, d);
        float t2 = __shfl_up_sync(0xFFFFFFFFu, i2, d);
        float t3 = __shfl_up_sync(0xFFFFFFFFu, i3, d);
        if (lane >= d) { i0 *= t0; i1 *= t1; i2 *= t2; i3 *= t3; }
    }
    float x0 = __shfl_up_sync(0xFFFFFFFFu, i0, 1);
    float x1 = __shfl_up_sync(0xFFFFFFFFu, i1, 1);
    float x2 = __shfl_up_sync(0xFFFFFFFFu, i2, 1);
    float x3 = __shfl_up_sync(0xFFFFFFFFu, i3, 1);
    if (lane == 0) { x0 = 1.0f; x1 = 1.0f; x2 = 1.0f; x3 = 1.0f; }
    float f0 = __shfl_sync(0xFFFFFFFFu, i0, 31);
    float f1 = __shfl_sync(0xFFFFFFFFu, i1, 31);
    float f2 = __shfl_sync(0xFFFFFFFFu, i2, 31);
    float f3 = __shfl_sync(0xFFFFFFFFu, i3, 31);

    // block carries (short scalar chain)
    float c0 = radius;
    float c1 = c0 * f0;
    float c2 = c1 * f1;
    float c3 = c2 * f2;
    float bp[4] = { c0 * x0, c1 * x1, c2 * x2, c3 * x3 };

    #pragma unroll
    for (int j = 0; j < 4; j++) {
        float bpj = bp[j];
        float4 o;
        o.x = bpj * cv0[j];
        o.y = (bpj * e1a[j]) * cv1[j];
        o.z = (bpj * e2a[j]) * cv2[j];
        o.w = (bpj * e3a[j]) * cv3[j];
        reinterpret_cast<float4*>(srow)[lane + 32 * j] = o;
    }
    if (lane == 0) srow[NFEAT] = c3 * f3;   // out[512] = radius * full product
    __syncwarp();

    // coalesced copy SMEM row -> GMEM (row pitch 513 floats), unguarded
    float* orow = out + (size_t)row * ROW_OUT;
    #pragma unroll
    for (int it = 0; it < 16; it++)
        orow[lane + 32 * it] = srow[lane + 32 * it];
    if (lane == 0) orow[NFEAT] = srow[NFEAT];
}

extern "C" void kernel_launch(void* const* d_in, const int* in_sizes, int n_in,
                              void* d_out, int out_size)
{
    int xi = 0;
    for (int i = 0; i < n_in; i++) if (in_sizes[i] > in_sizes[xi]) xi = i;
    int others[2]; int no = 0;
    for (int i = 0; i < n_in && no < 2; i++) if (i != xi) others[no++] = i;

    const float* x   = (const float*)d_in[xi];
    const float* sc  = (const float*)d_in[others[0]];   // scaling
    const float* rad = (const float*)d_in[others[1]];   // radius

    float* out = (float*)d_out;
    int nrows = in_sizes[xi] / NFEAT;

    // constants in double; PI truncated exactly as in the reference
    const double PI_d = 3.141592;
    double phiL = asin(pow(1e-6, 1.0 / 512.0));
    double phiU = PI_d / 2.0 * (1.0 - 0.01);
    if (phiU < phiL) phiL = phiU;
    double A = PI_d - 2.0 * phiL;
    float halfA = (float)(0.5 * A);          // ang = halfA*u + (halfA + phiL)
    float mid   = (float)(0.5 * A + phiL);

    int blocks = (nrows + WARPS_PER_BLOCK - 1) / WARPS_PER_BLOCK;
    spherization_kernel<<<blocks, WARPS_PER_BLOCK * 32>>>(
        x, sc, rad, out, nrows, halfA, mid);
}

// round 9
// speedup vs baseline: 1.0455x; 1.0036x over previous
#include <cuda_runtime.h>
#include <math.h>

// Spherization, per row r (512 features):
//   ang_j = A*sigmoid(scaling*x) + phiL
//   out[k]   = radius * prod_{j<k}(sin(ang_j)+eps) * sgn(cos_k)*(|cos(ang_k)|+eps)
//   out[512] = radius * prod_j (sin(ang_j)+eps)
// MUFU-minimized: sigmoid via MUFU.TANH (sigmoid(z)=(1+tanh(z/2))/2), so
//   ang = pi_t/2 + halfA*u,  u = tanh(scaling*x/2)
//   sin(ang) = cos(halfA*u - delta) ~= cos(halfA*u)  -> even 3-FMA poly in w=u^2
//   cos(ang) via MUFU.COS (keeps exact sign logic)
// 2 MUFU + 8 fma/alu issues per element. One warp per row; lane owns
// k = 128j+4l+m; 4 chained warp scans; SMEM-staged coalesced stores.

#define NFEAT 512
#define ROW_OUT 513
#define SROW_PITCH 520   // floats; 16B-aligned pitch
#define WARPS_PER_BLOCK 8

__global__ __launch_bounds__(WARPS_PER_BLOCK * 32)
void spherization_kernel(const float* __restrict__ x,
                         const float* __restrict__ scaling_p,
                         const float* __restrict__ radius_p,
                         float* __restrict__ out,
                         int nrows, float halfA, float mid,
                         float C3, float C2, float C1, float C0)
{
    __shared__ float sbuf[WARPS_PER_BLOCK * SROW_PITCH];

    const int wib  = threadIdx.x >> 5;
    const int lane = threadIdx.x & 31;
    const int row  = blockIdx.x * WARPS_PER_BLOCK + wib;
    if (row >= nrows) return;

    const float scaling = __ldg(scaling_p);
    const float radius  = __ldg(radius_p);
    const float hmul = 0.5f * scaling;     // t = hmul*x ; u = tanh(t)

    const float4* xr = reinterpret_cast<const float4*>(x + (size_t)row * NFEAT);
    float* srow = sbuf + wib * SROW_PITCH;

    // prefetch all loads (MLP=4)
    float4 v[4];
    #pragma unroll
    for (int j = 0; j < 4; j++) v[j] = xr[lane + 32 * j];

    float carry = radius;   // radius * (product of all elements in completed blocks)

    #pragma unroll
    for (int j = 0; j < 4; j++) {
        float vv[4] = {v[j].x, v[j].y, v[j].z, v[j].w};
        float sv[4], cv[4];
        #pragma unroll
        for (int m = 0; m < 4; m++) {
            float t = vv[m] * hmul;
            float u;  asm("tanh.approx.f32 %0, %1;" : "=f"(u) : "f"(t));
            float w = u * u;
            // sin(ang)+eps = cos(halfA*u)+eps : even poly, eps folded into C0
            sv[m] = fmaf(fmaf(fmaf(C3, w, C2), w, C1), w, C0);
            float ang = fmaf(halfA, u, mid);          // in [phiL, pi - phiL]
            float cs  = __cosf(ang);
            // sgn(cs)*(|cs|+eps) = cs + ((cs & signbit) | eps_bits)
            unsigned se;
            asm("lop3.b32 %0, %1, 0x80000000, 0x358637BD, 0xEA;"
                : "=r"(se) : "r"(__float_as_uint(cs)));
            cv[m] = cs + __uint_as_float(se);
        }
        // local exclusive prefixes within the 4 owned elements
        float e1  = sv[0];
        float e2  = e1 * sv[1];
        float e3  = e2 * sv[2];
        float tot = e3 * sv[3];

        // warp-inclusive scan of per-lane block totals
        float incl = tot;
        #pragma unroll
        for (int d = 1; d < 32; d <<= 1) {
            float t2 = __shfl_up_sync(0xFFFFFFFFu, incl, d);
            if (lane >= d) incl *= t2;
        }
        float excl = __shfl_up_sync(0xFFFFFFFFu, incl, 1);
        if (lane == 0) excl = 1.0f;

        float bp = carry * excl;  // radius * prod of everything before this lane

        float4 o;
        o.x = bp * cv[0];
        o.y = (bp * e1) * cv[1];
        o.z = (bp * e2) * cv[2];
        o.w = (bp * e3) * cv[3];
        reinterpret_cast<float4*>(srow)[lane + 32 * j] = o;

        carry *= __shfl_sync(0xFFFFFFFFu, incl, 31);
    }
    if (lane == 0) srow[NFEAT] = carry;   // out[512] = radius * full product
    __syncwarp();

    // coalesced copy SMEM row -> GMEM (row pitch 513 floats), unguarded
    float* orow = out + (size_t)row * ROW_OUT;
    #pragma unroll
    for (int it = 0; it < 16; it++)
        orow[lane + 32 * it] = srow[lane + 32 * it];
    if (lane == 0) orow[NFEAT] = srow[NFEAT];
}

extern "C" void kernel_launch(void* const* d_in, const int* in_sizes, int n_in,
                              void* d_out, int out_size)
{
    int xi = 0;
    for (int i = 0; i < n_in; i++) if (in_sizes[i] > in_sizes[xi]) xi = i;
    int others[2]; int no = 0;
    for (int i = 0; i < n_in && no < 2; i++) if (i != xi) others[no++] = i;

    const float* x   = (const float*)d_in[xi];
    const float* sc  = (const float*)d_in[others[0]];   // scaling
    const float* rad = (const float*)d_in[others[1]];   // radius

    float* out = (float*)d_out;
    int nrows = in_sizes[xi] / NFEAT;

    // constants in double; PI truncated exactly as in the reference
    const double PI_d = 3.141592;
    double phiL = asin(pow(1e-6, 1.0 / 512.0));
    double phiU = PI_d / 2.0 * (1.0 - 0.01);
    if (phiU < phiL) phiL = phiU;
    double A = PI_d - 2.0 * phiL;
    double hA = 0.5 * A;                     // ang = hA*u + (hA + phiL) = pi_t/2 + hA*u
    float halfA = (float)hA;
    float mid   = (float)(hA + phiL);

    // cos(hA*u) = 1 - h/2 w + h^2/24 w^2 - h^3/720 w^3,  w = u^2, h = hA^2
    double h = hA * hA;
    float C1 = (float)(-h / 2.0);
    float C2 = (float)(h * h / 24.0);
    float C3 = (float)(-h * h * h / 720.0);
    float C0 = 1.0f + 1e-6f;                 // +eps folded in

    int blocks = (nrows + WARPS_PER_BLOCK - 1) / WARPS_PER_BLOCK;
    spherization_kernel<<<blocks, WARPS_PER_BLOCK * 32>>>(
        x, sc, rad, out, nrows, halfA, mid, C3, C2, C1, C0);
}